// round 15
// baseline (speedup 1.0000x reference)
#include <cuda_runtime.h>
#include <cuda_fp16.h>
#include <math.h>
#include <stdint.h>

#define BB 2
#define SS 2048
#define DM 1024
#define NH 16
#define DK 64
#define NR (BB*SS)          // 4096 rows
#define OUT_ELEMS (NR*DM)               // 4194304
#define ATTN_ELEMS (BB*NH*SS*SS)        // 134217728

// ---- scratch (device globals; no allocation allowed) ----
__device__ float g_q[NR*DM];            // fp32 Q (only when attn requested)
__device__ float g_k[NR*DM];            // fp32 K (only when attn requested)
__device__ float g_m[BB*NH*SS];
__device__ float g_l[BB*NH*SS];
// fp16 operands
__device__ __half g_xh[NR*DM];                    // input x, single fp16
__device__ __half g_aoh[NR*DM];                   // attn output, single fp16
__device__ __half g_wth[3*DM*DM];                 // weights transposed [N][K], fp16
__device__ __half g_qh[NR*DM], g_ql[NR*DM];       // Q 2-term (score-path insurance)
__device__ __half g_kh[NR*DM];                    // K single
__device__ __half g_vh[NR*DM];                    // V single

__device__ __forceinline__ uint32_t smem_u32(const void* p) {
    uint32_t a;
    asm("{ .reg .u64 t; cvta.to.shared.u64 t, %1; cvt.u32.u64 %0, t; }" : "=r"(a) : "l"(p));
    return a;
}
#define CP_ASYNC16(dst, src) \
    asm volatile("cp.async.cg.shared.global [%0], [%1], 16;" :: "r"(dst), "l"(src))
#define CP_COMMIT() asm volatile("cp.async.commit_group;" ::: "memory")
#define CP_WAIT(n)  asm volatile("cp.async.wait_group %0;" :: "n"(n) : "memory")

__device__ __forceinline__ void mma16816(float c[4], const unsigned a[4], const unsigned b[2])
{
    asm volatile(
        "mma.sync.aligned.m16n8k16.row.col.f32.f16.f16.f32 "
        "{%0,%1,%2,%3}, {%4,%5,%6,%7}, {%8,%9}, {%0,%1,%2,%3};\n"
        : "+f"(c[0]), "+f"(c[1]), "+f"(c[2]), "+f"(c[3])
        : "r"(a[0]), "r"(a[1]), "r"(a[2]), "r"(a[3]), "r"(b[0]), "r"(b[1]));
}
__device__ __forceinline__ unsigned pack_h2(__half a, __half b)
{
    return (unsigned)__half_as_ushort(a) | ((unsigned)__half_as_ushort(b) << 16);
}
__device__ __forceinline__ unsigned split_hi2(float x, float y)
{
    return pack_h2(__float2half_rn(x), __float2half_rn(y));
}
__device__ __forceinline__ unsigned split_lo2(float x, float y)
{
    __half hx = __float2half_rn(x), hy = __float2half_rn(y);
    return pack_h2(__float2half_rn(x - __half2float(hx)),
                   __float2half_rn(y - __half2float(hy)));
}

// ============================================================
// convert fp32 x -> fp16 (single)
// ============================================================
__global__ __launch_bounds__(256) void conv_x(const float* __restrict__ src)
{
    int n = NR * DM;
    for (int i = blockIdx.x * blockDim.x + threadIdx.x; i < n; i += gridDim.x * blockDim.x)
        g_xh[i] = __float2half_rn(src[i]);
}

// ============================================================
// batched transpose: w[z] [K][N] fp32 -> slot z [N][K] fp16
// ============================================================
__global__ __launch_bounds__(256) void transpose_w3(
    const float* __restrict__ w0, const float* __restrict__ w1, const float* __restrict__ w2)
{
    __shared__ float tile[32][33];
    int z = blockIdx.z;
    const float* w = (z == 0) ? w0 : (z == 1 ? w1 : w2);
    size_t wo = (size_t)z * DM * DM;
    int tx = threadIdx.x, ty = threadIdx.y;
    int n0 = blockIdx.x * 32, k0 = blockIdx.y * 32;
#pragma unroll
    for (int j = 0; j < 32; j += 8)
        tile[ty + j][tx] = w[(size_t)(k0 + ty + j) * DM + n0 + tx];
    __syncthreads();
#pragma unroll
    for (int j = 0; j < 32; j += 8)
        g_wth[wo + (size_t)(n0 + ty + j) * DM + k0 + tx] =
            __float2half_rn(tile[tx][ty + j]);
}

// ============================================================
// fp16 TC GEMM v3: 128x64 CTA tile, 256 thr (4m x 2n warps,
// warp tile 32x32), cp.async 4-stage, 3 CTAs/SM.
// qkv=1: fused QKV (wsel = blockIdx.x>>4): Q -> hi/lo, K/V -> hi.
// qkv=0: O projection -> C_ext fp32 (A = g_aoh).
// ============================================================
#define AT_B   10240            // A: 128 rows * 80 B
#define BT_B   5120             // B:  64 rows * 80 B
#define STG    (AT_B + BT_B)    // 15360
#define NSTG   4
#define GP_SMEM (NSTG*STG)      // 61440

__global__ __launch_bounds__(256, 3) void gemm_pipe(
    int asel, const float* __restrict__ bias0, const float* __restrict__ bias1,
    const float* __restrict__ bias2, float* __restrict__ C_ext, int qkv, int f32qk)
{
    extern __shared__ char sm[];
    uint32_t sbase = smem_u32(sm);

    const __half* A = asel ? g_aoh : g_xh;
    int wsel = qkv ? (blockIdx.x >> 4) : 0;
    int col0 = (qkv ? (blockIdx.x & 15) : blockIdx.x) * 64;
    const float* bias = (wsel == 0) ? bias0 : (wsel == 1 ? bias1 : bias2);
    const __half* Wh = g_wth + (size_t)wsel * DM * DM;
    int row0 = blockIdx.y * 128;

    int tid = threadIdx.x;
    int lane = tid & 31, warp = tid >> 5;
    int wm = warp >> 1, wn = warp & 1;            // 4 m x 2 n warp grid
    int g = lane >> 2, t = lane & 3;

    float c[2][4][4];                              // [mt][nt][reg]
#pragma unroll
    for (int i = 0; i < 2; i++)
#pragma unroll
        for (int j = 0; j < 4; j++)
#pragma unroll
            for (int r = 0; r < 4; r++) c[i][j][r] = 0.f;

    // A loader: 128 rows, 2 thr/row, 2x uint4 each
    int lrA = tid >> 1, lcoA = (tid & 1) * 16;
    // B loader: 64 rows, 4 thr/row, 1x uint4 each
    int lrB = tid >> 2, lcoB = (tid & 3) * 8;
    const __half* pA = &A[(size_t)(row0 + lrA) * DM + lcoA];
    const __half* pB = &Wh[(size_t)(col0 + lrB) * DM + lcoB];
    uint32_t sa = sbase + lrA * 80 + lcoA * 2;
    uint32_t sb = sbase + AT_B + lrB * 80 + lcoB * 2;

#define LOAD_STAGE(ch, st) do {                                              \
        int k0_ = (ch) * 32;                                                 \
        CP_ASYNC16(sa + (st) * STG,       pA + k0_);                         \
        CP_ASYNC16(sa + (st) * STG + 16,  pA + k0_ + 8);                     \
        CP_ASYNC16(sb + (st) * STG,       pB + k0_);                         \
    } while (0)

#define SMA(st, off, rr, cc) \
    (*(const unsigned*)(sm + (st) * STG + (off) + (rr) * 80 + (cc) * 2))

    const int NCH = DM / 32;                      // 32 chunks
    LOAD_STAGE(0, 0); CP_COMMIT();
    LOAD_STAGE(1, 1); CP_COMMIT();
    LOAD_STAGE(2, 2); CP_COMMIT();

    for (int ch = 0; ch < NCH; ch++) {
        int st = ch & (NSTG - 1);
        if (ch + 3 < NCH) LOAD_STAGE(ch + 3, (ch + 3) & (NSTG - 1));
        CP_COMMIT();
        CP_WAIT(3);
        __syncthreads();

#pragma unroll
        for (int kk = 0; kk < 32; kk += 16) {
            unsigned ah[2][4], bh[4][2];
#pragma unroll
            for (int mt = 0; mt < 2; mt++) {
                int rb = wm * 32 + mt * 16;
                ah[mt][0] = SMA(st, 0, rb + g,     kk + 2 * t);
                ah[mt][1] = SMA(st, 0, rb + g + 8, kk + 2 * t);
                ah[mt][2] = SMA(st, 0, rb + g,     kk + 2 * t + 8);
                ah[mt][3] = SMA(st, 0, rb + g + 8, kk + 2 * t + 8);
            }
#pragma unroll
            for (int nt = 0; nt < 4; nt++) {
                int cb = wn * 32 + nt * 8;
                bh[nt][0] = SMA(st, AT_B, cb + g, kk + 2 * t);
                bh[nt][1] = SMA(st, AT_B, cb + g, kk + 2 * t + 8);
            }
#pragma unroll
            for (int mt = 0; mt < 2; mt++)
#pragma unroll
                for (int nt = 0; nt < 4; nt++)
                    mma16816(c[mt][nt], ah[mt], bh[nt]);
        }
        __syncthreads();
    }

#pragma unroll
    for (int mt = 0; mt < 2; mt++) {
#pragma unroll
        for (int nt = 0; nt < 4; nt++) {
            int col = col0 + wn * 32 + nt * 8 + 2 * t;
            float bx = bias[col], by = bias[col + 1];
            int r0 = row0 + wm * 32 + mt * 16 + g;
            float2 o0 = { c[mt][nt][0] + bx, c[mt][nt][1] + by };
            float2 o1 = { c[mt][nt][2] + bx, c[mt][nt][3] + by };
            if (!qkv) {
                *(float2*)&C_ext[(size_t)r0 * DM + col] = o0;
                *(float2*)&C_ext[(size_t)(r0 + 8) * DM + col] = o1;
            } else {
                if (wsel == 0) {
                    if (f32qk) {
                        *(float2*)&g_q[(size_t)r0 * DM + col] = o0;
                        *(float2*)&g_q[(size_t)(r0 + 8) * DM + col] = o1;
                    }
                    *(unsigned*)&g_qh[(size_t)r0 * DM + col]       = split_hi2(o0.x, o0.y);
                    *(unsigned*)&g_ql[(size_t)r0 * DM + col]       = split_lo2(o0.x, o0.y);
                    *(unsigned*)&g_qh[(size_t)(r0 + 8) * DM + col] = split_hi2(o1.x, o1.y);
                    *(unsigned*)&g_ql[(size_t)(r0 + 8) * DM + col] = split_lo2(o1.x, o1.y);
                } else if (wsel == 1) {
                    if (f32qk) {
                        *(float2*)&g_k[(size_t)r0 * DM + col] = o0;
                        *(float2*)&g_k[(size_t)(r0 + 8) * DM + col] = o1;
                    }
                    *(unsigned*)&g_kh[(size_t)r0 * DM + col]       = split_hi2(o0.x, o0.y);
                    *(unsigned*)&g_kh[(size_t)(r0 + 8) * DM + col] = split_hi2(o1.x, o1.y);
                } else {
                    *(unsigned*)&g_vh[(size_t)r0 * DM + col]       = split_hi2(o0.x, o0.y);
                    *(unsigned*)&g_vh[(size_t)(r0 + 8) * DM + col] = split_hi2(o1.x, o1.y);
                }
            }
        }
    }
}

// ============================================================
// Flash attention (unchanged): BQ=128, BKV=32, 256 thr.
// QK^T 2-term (Q split, K single); PV single.
// ============================================================
#define FQH 0
#define FQL 18432
#define FKH 36864
#define FVH 41472
#define FPAD 46592
#define F_SMEM 46720

#define QHF(r, c)  (*(const unsigned*)(sm + FQH + (r) * 144 + (c) * 2))
#define QLF(r, c)  (*(const unsigned*)(sm + FQL + (r) * 144 + (c) * 2))
#define KHF(r, c)  (*(const unsigned*)(sm + FKH + (r) * 144 + (c) * 2))
#define VTHF(d, k) (*(const unsigned*)(sm + FVH + (d) * 80 + (k) * 2))

__global__ __launch_bounds__(256) void flash_tc2(const int* __restrict__ token_ids)
{
    extern __shared__ char sm[];
    int* padf = (int*)(sm + FPAD);

    int qb = blockIdx.x, h = blockIdx.y, b = blockIdx.z;
    int q0 = qb * 128;
    int tid = threadIdx.x, lane = tid & 31, w = tid >> 5;
    int g = lane >> 2, t = lane & 3;

    // Q tile fill: 128 rows x 64 fp16, hi+lo
    {
        int r = tid >> 1, c0 = (tid & 1) * 32;
        const uint4* ph = (const uint4*)&g_qh[(size_t)(b * SS + q0 + r) * DM + h * DK + c0];
        const uint4* pl = (const uint4*)&g_ql[(size_t)(b * SS + q0 + r) * DM + h * DK + c0];
#pragma unroll
        for (int j = 0; j < 4; j++) {
            *(uint4*)(sm + FQH + r * 144 + c0 * 2 + j * 16) = ph[j];
            *(uint4*)(sm + FQL + r * 144 + c0 * 2 + j * 16) = pl[j];
        }
    }

    float o[8][4];
#pragma unroll
    for (int i = 0; i < 8; i++)
#pragma unroll
        for (int j = 0; j < 4; j++) o[i][j] = 0.f;
    float m0 = -INFINITY, m1 = -INFINITY, l0 = 0.f, l1 = 0.f;

    int row0 = q0 + w * 16 + g;
    int row1 = row0 + 8;

    int kb_max = 4 * qb + 3;
    for (int kb = 0; kb <= kb_max; kb++) {
        int kv0 = kb * 32;
        if (tid < 128) {        // K tile: 32 x 64 (hi only)
            int r = tid >> 2, c0 = (tid & 3) * 16;
            size_t gi = (size_t)(b * SS + kv0 + r) * DM + h * DK + c0;
            const uint4* ph = (const uint4*)&g_kh[gi];
            *(uint4*)(sm + FKH + r * 144 + c0 * 2)      = ph[0];
            *(uint4*)(sm + FKH + r * 144 + c0 * 2 + 16) = ph[1];
        } else {                // V tile transposed: Vt[64][32]
            int t2 = tid - 128;
            int r = t2 >> 2, c0 = (t2 & 3) * 16;
            size_t gi = (size_t)(b * SS + kv0 + r) * DM + h * DK + c0;
            __half vh[16];
            *(uint4*)&vh[0] = ((const uint4*)&g_vh[gi])[0];
            *(uint4*)&vh[8] = ((const uint4*)&g_vh[gi])[1];
#pragma unroll
            for (int i = 0; i < 16; i++)
                *(__half*)(sm + FVH + (c0 + i) * 80 + r * 2) = vh[i];
        }
        if (tid < 32) padf[tid] = (token_ids[b * SS + kv0 + tid] == 0);
        __syncthreads();

        // S = Q K^T : 2-term (Q hi/lo, K single)
        float s[4][4];
#pragma unroll
        for (int nt = 0; nt < 4; nt++)
#pragma unroll
            for (int r = 0; r < 4; r++) s[nt][r] = 0.f;

        int rb = w * 16;
#pragma unroll
        for (int kc = 0; kc < 4; kc++) {
            int kk = kc * 16;
            unsigned aqh[4], aql[4];
            aqh[0] = QHF(rb + g,     kk + 2 * t);
            aqh[1] = QHF(rb + g + 8, kk + 2 * t);
            aqh[2] = QHF(rb + g,     kk + 2 * t + 8);
            aqh[3] = QHF(rb + g + 8, kk + 2 * t + 8);
            aql[0] = QLF(rb + g,     kk + 2 * t);
            aql[1] = QLF(rb + g + 8, kk + 2 * t);
            aql[2] = QLF(rb + g,     kk + 2 * t + 8);
            aql[3] = QLF(rb + g + 8, kk + 2 * t + 8);
#pragma unroll
            for (int nt = 0; nt < 4; nt++) {
                unsigned bh[2];
                bh[0] = KHF(nt * 8 + g, kk + 2 * t);
                bh[1] = KHF(nt * 8 + g, kk + 2 * t + 8);
                mma16816(s[nt], aqh, bh);
                mma16816(s[nt], aql, bh);
            }
        }

        // scale + mask
#pragma unroll
        for (int nt = 0; nt < 4; nt++) {
            int c0 = nt * 8 + 2 * t;
            int k0i = kv0 + c0, k1i = k0i + 1;
            int p0 = padf[c0], p1 = padf[c0 + 1];
            float v0 = s[nt][0] * 0.125f, v1 = s[nt][1] * 0.125f;
            float v2 = s[nt][2] * 0.125f, v3 = s[nt][3] * 0.125f;
            s[nt][0] = (k0i > row0 || p0) ? -1e9f : v0;
            s[nt][1] = (k1i > row0 || p1) ? -1e9f : v1;
            s[nt][2] = (k0i > row1 || p0) ? -1e9f : v2;
            s[nt][3] = (k1i > row1 || p1) ? -1e9f : v3;
        }

        float rmax0 = -INFINITY, rmax1 = -INFINITY;
#pragma unroll
        for (int nt = 0; nt < 4; nt++) {
            rmax0 = fmaxf(rmax0, fmaxf(s[nt][0], s[nt][1]));
            rmax1 = fmaxf(rmax1, fmaxf(s[nt][2], s[nt][3]));
        }
#pragma unroll
        for (int off = 1; off <= 2; off <<= 1) {
            rmax0 = fmaxf(rmax0, __shfl_xor_sync(0xffffffffu, rmax0, off));
            rmax1 = fmaxf(rmax1, __shfl_xor_sync(0xffffffffu, rmax1, off));
        }
        float mn0 = fmaxf(m0, rmax0), mn1 = fmaxf(m1, rmax1);

        float rs0 = 0.f, rs1 = 0.f;
#pragma unroll
        for (int nt = 0; nt < 4; nt++) {
            s[nt][0] = __expf(s[nt][0] - mn0);
            s[nt][1] = __expf(s[nt][1] - mn0);
            s[nt][2] = __expf(s[nt][2] - mn1);
            s[nt][3] = __expf(s[nt][3] - mn1);
            rs0 += s[nt][0] + s[nt][1];
            rs1 += s[nt][2] + s[nt][3];
        }
#pragma unroll
        for (int off = 1; off <= 2; off <<= 1) {
            rs0 += __shfl_xor_sync(0xffffffffu, rs0, off);
            rs1 += __shfl_xor_sync(0xffffffffu, rs1, off);
        }
        float sc0 = __expf(m0 - mn0), sc1 = __expf(m1 - mn1);
        l0 = l0 * sc0 + rs0;
        l1 = l1 * sc1 + rs1;
        m0 = mn0; m1 = mn1;
#pragma unroll
        for (int ot = 0; ot < 8; ot++) {
            o[ot][0] *= sc0; o[ot][1] *= sc0;
            o[ot][2] *= sc1; o[ot][3] *= sc1;
        }

        // PV: P single fp16, V single
#pragma unroll
        for (int kc = 0; kc < 2; kc++) {
            unsigned ph[4];
            {
                int n0i = 2 * kc, n1i = 2 * kc + 1;
                ph[0] = split_hi2(s[n0i][0], s[n0i][1]);
                ph[1] = split_hi2(s[n0i][2], s[n0i][3]);
                ph[2] = split_hi2(s[n1i][0], s[n1i][1]);
                ph[3] = split_hi2(s[n1i][2], s[n1i][3]);
            }
            int kk = kc * 16;
#pragma unroll
            for (int ot = 0; ot < 8; ot++) {
                unsigned bvh[2];
                bvh[0] = VTHF(ot * 8 + g, kk + 2 * t);
                bvh[1] = VTHF(ot * 8 + g, kk + 2 * t + 8);
                mma16816(o[ot], ph, bvh);
            }
        }
        __syncthreads();
    }

    bool deg0 = !(m0 > -1e8f);
    bool deg1 = !(m1 > -1e8f);
    float inv0 = deg0 ? 0.f : 1.f / l0;
    float inv1 = deg1 ? 0.f : 1.f / l1;
#pragma unroll
    for (int ot = 0; ot < 8; ot++) {
        int col = h * DK + ot * 8 + 2 * t;
        float2 o0 = { o[ot][0] * inv0, o[ot][1] * inv0 };
        float2 o1 = { o[ot][2] * inv1, o[ot][3] * inv1 };
        if (deg0) {
            float s0 = 0.f, s1 = 0.f;
            const __half* vp = &g_vh[(size_t)(b * SS) * DM + col];
            for (int kv = 0; kv < SS; kv++) {
                s0 += __half2float(vp[(size_t)kv * DM]);
                s1 += __half2float(vp[(size_t)kv * DM + 1]);
            }
            o0.x = s0 / SS; o0.y = s1 / SS;
        }
        if (deg1) {
            float s0 = 0.f, s1 = 0.f;
            const __half* vp = &g_vh[(size_t)(b * SS) * DM + col];
            for (int kv = 0; kv < SS; kv++) {
                s0 += __half2float(vp[(size_t)kv * DM]);
                s1 += __half2float(vp[(size_t)kv * DM + 1]);
            }
            o1.x = s0 / SS; o1.y = s1 / SS;
        }
        *(unsigned*)&g_aoh[(size_t)(b * SS + row0) * DM + col] = split_hi2(o0.x, o0.y);
        *(unsigned*)&g_aoh[(size_t)(b * SS + row1) * DM + col] = split_hi2(o1.x, o1.y);
    }
    if (t == 0) {
        int gi0 = (b * NH + h) * SS + row0;
        int gi1 = (b * NH + h) * SS + row1;
        g_m[gi0] = deg0 ? -1e9f : m0;
        g_l[gi0] = deg0 ? (float)SS : l0;
        g_m[gi1] = deg1 ? -1e9f : m1;
        g_l[gi1] = deg1 ? (float)SS : l1;
    }
}

// ============================================================
// Optional second pass: full attention probabilities
// ============================================================
__global__ __launch_bounds__(256) void attn_write(
    const int* __restrict__ token_ids, float* __restrict__ attn)
{
    int kvb = blockIdx.x, qb = blockIdx.y;
    int bh = blockIdx.z;
    int b = bh >> 4, h = bh & 15;
    int q0 = qb * 64, kv0 = kvb * 64;
    int tid = threadIdx.x;
    int tx = tid & 15, ty = tid >> 4;

    if (kv0 > q0 + 63) {
#pragma unroll
        for (int i = 0; i < 4; i++) {
            int q = q0 + ty * 4 + i;
            int gi = (b * NH + h) * SS + q;
            float m = g_m[gi];
            float val = (m <= -1e8f) ? (1.f / g_l[gi]) : 0.f;
            float4 o = { val, val, val, val };
            *(float4*)&attn[((size_t)(b * NH + h) * SS + q) * SS + kv0 + tx * 4] = o;
        }
        return;
    }

    __shared__ float Qs[64][65];
    __shared__ float Ks2[64][65];
    __shared__ int padf[64];
    {
        int r = tid >> 2;
        int d0 = (tid & 3) * 16;
        const float* qp = &g_q[(size_t)(b * SS + q0 + r) * DM + h * DK + d0];
        const float* kp = &g_k[(size_t)(b * SS + kv0 + r) * DM + h * DK + d0];
#pragma unroll
        for (int i = 0; i < 16; i += 4) {
            float4 v4 = *(const float4*)(qp + i);
            Qs[d0 + i + 0][r] = v4.x; Qs[d0 + i + 1][r] = v4.y;
            Qs[d0 + i + 2][r] = v4.z; Qs[d0 + i + 3][r] = v4.w;
            float4 k4 = *(const float4*)(kp + i);
            Ks2[d0 + i + 0][r] = k4.x; Ks2[d0 + i + 1][r] = k4.y;
            Ks2[d0 + i + 2][r] = k4.z; Ks2[d0 + i + 3][r] = k4.w;
        }
    }
    if (tid < 64) padf[tid] = (token_ids[b * SS + kv0 + tid] == 0);
    __syncthreads();

    float s[4][4];
#pragma unroll
    for (int i = 0; i < 4; i++)
#pragma unroll
        for (int j = 0; j < 4; j++) s[i][j] = 0.f;
#pragma unroll
    for (int kk = 0; kk < 64; kk++) {
        float qv[4], kv_[4];
#pragma unroll
        for (int i = 0; i < 4; i++) qv[i] = Qs[kk][ty * 4 + i];
#pragma unroll
        for (int j = 0; j < 4; j++) kv_[j] = Ks2[kk][tx * 4 + j];
#pragma unroll
        for (int i = 0; i < 4; i++)
#pragma unroll
            for (int j = 0; j < 4; j++)
                s[i][j] = fmaf(qv[i], kv_[j], s[i][j]);
    }
#pragma unroll
    for (int i = 0; i < 4; i++) {
        int q = q0 + ty * 4 + i;
        int gi = (b * NH + h) * SS + q;
        float m = g_m[gi];
        float invl = 1.f / g_l[gi];
        float4 o;
        float ov[4];
#pragma unroll
        for (int j = 0; j < 4; j++) {
            int kvi = kv0 + tx * 4 + j;
            float v = s[i][j] * 0.125f;
            if (kvi > q || padf[tx * 4 + j]) v = -1e9f;
            ov[j] = __expf(v - m) * invl;
        }
        o.x = ov[0]; o.y = ov[1]; o.z = ov[2]; o.w = ov[3];
        *(float4*)&attn[((size_t)(b * NH + h) * SS + q) * SS + kv0 + tx * 4] = o;
    }
}

// ============================================================
extern "C" void kernel_launch(void* const* d_in, const int* in_sizes, int n_in,
                              void* d_out, int out_size)
{
    const float* x  = (const float*)d_in[0];
    const int*  tok = (const int*)d_in[1];
    const float* wq = (const float*)d_in[2];
    const float* bq = (const float*)d_in[3];
    const float* wk = (const float*)d_in[4];
    const float* bk = (const float*)d_in[5];
    const float* wv = (const float*)d_in[6];
    const float* bv = (const float*)d_in[7];
    const float* wo = (const float*)d_in[8];
    const float* bo = (const float*)d_in[9];
    float* out = (float*)d_out;

    cudaFuncSetAttribute(gemm_pipe, cudaFuncAttributeMaxDynamicSharedMemorySize, GP_SMEM);
    cudaFuncSetAttribute(flash_tc2, cudaFuncAttributeMaxDynamicSharedMemorySize, F_SMEM);

    bool want_out  = (out_size != ATTN_ELEMS);
    bool want_attn = (out_size >= ATTN_ELEMS);
    float* attn_ptr = nullptr;
    if (out_size == ATTN_ELEMS) attn_ptr = out;
    else if (out_size >= OUT_ELEMS + ATTN_ELEMS) attn_ptr = out + OUT_ELEMS;

    dim3 bT(32, 8);

    conv_x<<<1024, 256>>>(x);
    transpose_w3<<<dim3(32, 32, 3), bT>>>(wq, wk, wv);
    gemm_pipe<<<dim3(48, 32), 256, GP_SMEM>>>(0, bq, bk, bv, nullptr, 1,
                                              want_attn ? 1 : 0);

    flash_tc2<<<dim3(SS / 128, NH, BB), 256, F_SMEM>>>(tok);

    if (want_out) {
        transpose_w3<<<dim3(32, 32, 1), bT>>>(wo, wo, wo);
        gemm_pipe<<<dim3(16, 32), 256, GP_SMEM>>>(1, bo, bo, bo, out, 0, 0);
    }
    if (want_attn && attn_ptr)
        attn_write<<<dim3(SS / 64, SS / 64, BB * NH), 256>>>(tok, attn_ptr);
}

// round 16
// speedup vs baseline: 1.0771x; 1.0771x over previous
#include <cuda_runtime.h>
#include <cuda_fp16.h>
#include <math.h>
#include <stdint.h>

#define BB 2
#define SS 2048
#define DM 1024
#define NH 16
#define DK 64
#define NR (BB*SS)          // 4096 rows
#define OUT_ELEMS (NR*DM)               // 4194304
#define ATTN_ELEMS (BB*NH*SS*SS)        // 134217728

// ---- scratch (device globals; no allocation allowed) ----
__device__ float g_q[NR*DM];            // fp32 Q (only when attn requested)
__device__ float g_k[NR*DM];            // fp32 K (only when attn requested)
__device__ float g_m[BB*NH*SS];
__device__ float g_l[BB*NH*SS];
// fp16 operands
__device__ __half g_xh[NR*DM];                    // input x, single fp16
__device__ __half g_aoh[NR*DM];                   // attn output, single fp16
__device__ __half g_wth[3*DM*DM];                 // weights transposed [N][K], fp16
__device__ __half g_qh[NR*DM];                    // Q single
__device__ __half g_kh[NR*DM];                    // K single
__device__ __half g_vh[NR*DM];                    // V single

__device__ __forceinline__ uint32_t smem_u32(const void* p) {
    uint32_t a;
    asm("{ .reg .u64 t; cvta.to.shared.u64 t, %1; cvt.u32.u64 %0, t; }" : "=r"(a) : "l"(p));
    return a;
}
#define CP_ASYNC16(dst, src) \
    asm volatile("cp.async.cg.shared.global [%0], [%1], 16;" :: "r"(dst), "l"(src))
#define CP_COMMIT() asm volatile("cp.async.commit_group;" ::: "memory")
#define CP_WAIT(n)  asm volatile("cp.async.wait_group %0;" :: "n"(n) : "memory")

__device__ __forceinline__ void mma16816(float c[4], const unsigned a[4], const unsigned b[2])
{
    asm volatile(
        "mma.sync.aligned.m16n8k16.row.col.f32.f16.f16.f32 "
        "{%0,%1,%2,%3}, {%4,%5,%6,%7}, {%8,%9}, {%0,%1,%2,%3};\n"
        : "+f"(c[0]), "+f"(c[1]), "+f"(c[2]), "+f"(c[3])
        : "r"(a[0]), "r"(a[1]), "r"(a[2]), "r"(a[3]), "r"(b[0]), "r"(b[1]));
}
__device__ __forceinline__ unsigned pack_h2(__half a, __half b)
{
    return (unsigned)__half_as_ushort(a) | ((unsigned)__half_as_ushort(b) << 16);
}
__device__ __forceinline__ unsigned split_hi2(float x, float y)
{
    return pack_h2(__float2half_rn(x), __float2half_rn(y));
}

// ============================================================
// convert fp32 x -> fp16 (single)
// ============================================================
__global__ __launch_bounds__(256) void conv_x(const float* __restrict__ src)
{
    int n = NR * DM;
    for (int i = blockIdx.x * blockDim.x + threadIdx.x; i < n; i += gridDim.x * blockDim.x)
        g_xh[i] = __float2half_rn(src[i]);
}

// ============================================================
// batched transpose: w[z] [K][N] fp32 -> slot z [N][K] fp16
// ============================================================
__global__ __launch_bounds__(256) void transpose_w3(
    const float* __restrict__ w0, const float* __restrict__ w1, const float* __restrict__ w2)
{
    __shared__ float tile[32][33];
    int z = blockIdx.z;
    const float* w = (z == 0) ? w0 : (z == 1 ? w1 : w2);
    size_t wo = (size_t)z * DM * DM;
    int tx = threadIdx.x, ty = threadIdx.y;
    int n0 = blockIdx.x * 32, k0 = blockIdx.y * 32;
#pragma unroll
    for (int j = 0; j < 32; j += 8)
        tile[ty + j][tx] = w[(size_t)(k0 + ty + j) * DM + n0 + tx];
    __syncthreads();
#pragma unroll
    for (int j = 0; j < 32; j += 8)
        g_wth[wo + (size_t)(n0 + ty + j) * DM + k0 + tx] =
            __float2half_rn(tile[tx][ty + j]);
}

// ============================================================
// fp16 TC GEMM (R12 shape): 128x128 tile, 256 thr, cp.async 2-stage.
// qkv=1: fused QKV (wsel = blockIdx.x>>3): outputs single fp16 q/k/v.
// qkv=0: O projection -> C_ext fp32 (A = g_aoh).
// ============================================================
#define TILE_B   10240            // 128 rows * 80 B
#define STAGE_B  (2*TILE_B)       // A, B
#define GP_SMEM  (2*STAGE_B)      // 40960

__global__ __launch_bounds__(256) void gemm_pipe(
    int asel, const float* __restrict__ bias0, const float* __restrict__ bias1,
    const float* __restrict__ bias2, float* __restrict__ C_ext, int qkv, int f32qk)
{
    extern __shared__ char sm[];
    uint32_t sbase = smem_u32(sm);

    const __half* A = asel ? g_aoh : g_xh;
    int wsel = qkv ? (blockIdx.x >> 3) : 0;
    int col0 = (qkv ? (blockIdx.x & 7) : blockIdx.x) * 128;
    const float* bias = (wsel == 0) ? bias0 : (wsel == 1 ? bias1 : bias2);
    const __half* Wh = g_wth + (size_t)wsel * DM * DM;
    int row0 = blockIdx.y * 128;

    int tid = threadIdx.x;
    int lane = tid & 31, warp = tid >> 5;
    int wm = warp & 1, wn = warp >> 1;            // 2 x 4 warp grid
    int g = lane >> 2, t = lane & 3;

    float c[4][4][4];
#pragma unroll
    for (int i = 0; i < 4; i++)
#pragma unroll
        for (int j = 0; j < 4; j++)
#pragma unroll
            for (int r = 0; r < 4; r++) c[i][j][r] = 0.f;

    int lr = tid >> 1;
    int lco = (tid & 1) * 16;
    const __half* pA = &A[(size_t)(row0 + lr) * DM + lco];
    const __half* pB = &Wh[(size_t)(col0 + lr) * DM + lco];
    uint32_t sA = sbase + lr * 80 + lco * 2;

#define LOAD_STAGE(ch, st) do {                                              \
        int k0_ = (ch) * 32;                                                 \
        uint32_t d_ = sA + (st) * STAGE_B;                                   \
        CP_ASYNC16(d_,                 pA + k0_);                            \
        CP_ASYNC16(d_ + 16,            pA + k0_ + 8);                        \
        CP_ASYNC16(d_ + TILE_B,        pB + k0_);                            \
        CP_ASYNC16(d_ + TILE_B + 16,   pB + k0_ + 8);                        \
    } while (0)

#define SMA(st, off, rr, cc) \
    (*(const unsigned*)(sm + (st) * STAGE_B + (off) + (rr) * 80 + (cc) * 2))

    const int NCH = DM / 32;
    LOAD_STAGE(0, 0);
    CP_COMMIT();

    for (int ch = 0; ch < NCH; ch++) {
        int st = ch & 1;
        if (ch + 1 < NCH) {
            LOAD_STAGE(ch + 1, (ch + 1) & 1);
            CP_COMMIT();
            CP_WAIT(1);
        } else {
            CP_WAIT(0);
        }
        __syncthreads();

#pragma unroll
        for (int kk = 0; kk < 32; kk += 16) {
            unsigned ah[4][4], bh[4][2];
#pragma unroll
            for (int mt = 0; mt < 4; mt++) {
                int rb = wm * 64 + mt * 16;
                ah[mt][0] = SMA(st, 0, rb + g,     kk + 2 * t);
                ah[mt][1] = SMA(st, 0, rb + g + 8, kk + 2 * t);
                ah[mt][2] = SMA(st, 0, rb + g,     kk + 2 * t + 8);
                ah[mt][3] = SMA(st, 0, rb + g + 8, kk + 2 * t + 8);
            }
#pragma unroll
            for (int nt = 0; nt < 4; nt++) {
                int cb = wn * 32 + nt * 8;
                bh[nt][0] = SMA(st, TILE_B, cb + g, kk + 2 * t);
                bh[nt][1] = SMA(st, TILE_B, cb + g, kk + 2 * t + 8);
            }
#pragma unroll
            for (int mt = 0; mt < 4; mt++)
#pragma unroll
                for (int nt = 0; nt < 4; nt++)
                    mma16816(c[mt][nt], ah[mt], bh[nt]);
        }
        __syncthreads();
    }

#pragma unroll
    for (int mt = 0; mt < 4; mt++) {
#pragma unroll
        for (int nt = 0; nt < 4; nt++) {
            int col = col0 + wn * 32 + nt * 8 + 2 * t;
            float bx = bias[col], by = bias[col + 1];
            int r0 = row0 + wm * 64 + mt * 16 + g;
            float2 o0 = { c[mt][nt][0] + bx, c[mt][nt][1] + by };
            float2 o1 = { c[mt][nt][2] + bx, c[mt][nt][3] + by };
            if (!qkv) {
                *(float2*)&C_ext[(size_t)r0 * DM + col] = o0;
                *(float2*)&C_ext[(size_t)(r0 + 8) * DM + col] = o1;
            } else {
                __half* Ch = (wsel == 0) ? g_qh : (wsel == 1 ? g_kh : g_vh);
                if (f32qk && wsel == 0) {
                    *(float2*)&g_q[(size_t)r0 * DM + col] = o0;
                    *(float2*)&g_q[(size_t)(r0 + 8) * DM + col] = o1;
                }
                if (f32qk && wsel == 1) {
                    *(float2*)&g_k[(size_t)r0 * DM + col] = o0;
                    *(float2*)&g_k[(size_t)(r0 + 8) * DM + col] = o1;
                }
                *(unsigned*)&Ch[(size_t)r0 * DM + col]       = split_hi2(o0.x, o0.y);
                *(unsigned*)&Ch[(size_t)(r0 + 8) * DM + col] = split_hi2(o1.x, o1.y);
            }
        }
    }
}

// ============================================================
// Flash attention: BQ=128, BKV=32, 256 thr. Heavy-first qb order.
// QK^T single fp16; PV single fp16.
// ============================================================
#define FQH 0
#define FKH 18432
#define FVH 23040
#define FPAD 28160
#define F_SMEM 28288

#define QHF(r, c)  (*(const unsigned*)(sm + FQH + (r) * 144 + (c) * 2))
#define KHF(r, c)  (*(const unsigned*)(sm + FKH + (r) * 144 + (c) * 2))
#define VTHF(d, k) (*(const unsigned*)(sm + FVH + (d) * 80 + (k) * 2))

__global__ __launch_bounds__(256) void flash_tc2(const int* __restrict__ token_ids)
{
    extern __shared__ char sm[];
    int* padf = (int*)(sm + FPAD);

    int qb = (gridDim.x - 1) - blockIdx.x;        // heavy CTAs first
    int h = blockIdx.y, b = blockIdx.z;
    int q0 = qb * 128;
    int tid = threadIdx.x, lane = tid & 31, w = tid >> 5;
    int g = lane >> 2, t = lane & 3;

    // Q tile fill: 128 rows x 64 fp16
    {
        int r = tid >> 1, c0 = (tid & 1) * 32;
        const uint4* ph = (const uint4*)&g_qh[(size_t)(b * SS + q0 + r) * DM + h * DK + c0];
#pragma unroll
        for (int j = 0; j < 4; j++)
            *(uint4*)(sm + FQH + r * 144 + c0 * 2 + j * 16) = ph[j];
    }

    float o[8][4];
#pragma unroll
    for (int i = 0; i < 8; i++)
#pragma unroll
        for (int j = 0; j < 4; j++) o[i][j] = 0.f;
    float m0 = -INFINITY, m1 = -INFINITY, l0 = 0.f, l1 = 0.f;

    int row0 = q0 + w * 16 + g;
    int row1 = row0 + 8;

    int kb_max = 4 * qb + 3;
    for (int kb = 0; kb <= kb_max; kb++) {
        int kv0 = kb * 32;
        if (tid < 128) {        // K tile: 32 x 64
            int r = tid >> 2, c0 = (tid & 3) * 16;
            size_t gi = (size_t)(b * SS + kv0 + r) * DM + h * DK + c0;
            const uint4* ph = (const uint4*)&g_kh[gi];
            *(uint4*)(sm + FKH + r * 144 + c0 * 2)      = ph[0];
            *(uint4*)(sm + FKH + r * 144 + c0 * 2 + 16) = ph[1];
        } else {                // V tile transposed: Vt[64][32]
            int t2 = tid - 128;
            int r = t2 >> 2, c0 = (t2 & 3) * 16;
            size_t gi = (size_t)(b * SS + kv0 + r) * DM + h * DK + c0;
            __half vh[16];
            *(uint4*)&vh[0] = ((const uint4*)&g_vh[gi])[0];
            *(uint4*)&vh[8] = ((const uint4*)&g_vh[gi])[1];
#pragma unroll
            for (int i = 0; i < 16; i++)
                *(__half*)(sm + FVH + (c0 + i) * 80 + r * 2) = vh[i];
        }
        if (tid < 32) padf[tid] = (token_ids[b * SS + kv0 + tid] == 0);
        __syncthreads();

        // S = Q K^T (single fp16)
        float s[4][4];
#pragma unroll
        for (int nt = 0; nt < 4; nt++)
#pragma unroll
            for (int r = 0; r < 4; r++) s[nt][r] = 0.f;

        int rb = w * 16;
#pragma unroll
        for (int kc = 0; kc < 4; kc++) {
            int kk = kc * 16;
            unsigned aqh[4];
            aqh[0] = QHF(rb + g,     kk + 2 * t);
            aqh[1] = QHF(rb + g + 8, kk + 2 * t);
            aqh[2] = QHF(rb + g,     kk + 2 * t + 8);
            aqh[3] = QHF(rb + g + 8, kk + 2 * t + 8);
#pragma unroll
            for (int nt = 0; nt < 4; nt++) {
                unsigned bh[2];
                bh[0] = KHF(nt * 8 + g, kk + 2 * t);
                bh[1] = KHF(nt * 8 + g, kk + 2 * t + 8);
                mma16816(s[nt], aqh, bh);
            }
        }

        // scale + mask
#pragma unroll
        for (int nt = 0; nt < 4; nt++) {
            int c0 = nt * 8 + 2 * t;
            int k0i = kv0 + c0, k1i = k0i + 1;
            int p0 = padf[c0], p1 = padf[c0 + 1];
            float v0 = s[nt][0] * 0.125f, v1 = s[nt][1] * 0.125f;
            float v2 = s[nt][2] * 0.125f, v3 = s[nt][3] * 0.125f;
            s[nt][0] = (k0i > row0 || p0) ? -1e9f : v0;
            s[nt][1] = (k1i > row0 || p1) ? -1e9f : v1;
            s[nt][2] = (k0i > row1 || p0) ? -1e9f : v2;
            s[nt][3] = (k1i > row1 || p1) ? -1e9f : v3;
        }

        float rmax0 = -INFINITY, rmax1 = -INFINITY;
#pragma unroll
        for (int nt = 0; nt < 4; nt++) {
            rmax0 = fmaxf(rmax0, fmaxf(s[nt][0], s[nt][1]));
            rmax1 = fmaxf(rmax1, fmaxf(s[nt][2], s[nt][3]));
        }
#pragma unroll
        for (int off = 1; off <= 2; off <<= 1) {
            rmax0 = fmaxf(rmax0, __shfl_xor_sync(0xffffffffu, rmax0, off));
            rmax1 = fmaxf(rmax1, __shfl_xor_sync(0xffffffffu, rmax1, off));
        }
        float mn0 = fmaxf(m0, rmax0), mn1 = fmaxf(m1, rmax1);

        float rs0 = 0.f, rs1 = 0.f;
#pragma unroll
        for (int nt = 0; nt < 4; nt++) {
            s[nt][0] = __expf(s[nt][0] - mn0);
            s[nt][1] = __expf(s[nt][1] - mn0);
            s[nt][2] = __expf(s[nt][2] - mn1);
            s[nt][3] = __expf(s[nt][3] - mn1);
            rs0 += s[nt][0] + s[nt][1];
            rs1 += s[nt][2] + s[nt][3];
        }
#pragma unroll
        for (int off = 1; off <= 2; off <<= 1) {
            rs0 += __shfl_xor_sync(0xffffffffu, rs0, off);
            rs1 += __shfl_xor_sync(0xffffffffu, rs1, off);
        }
        float sc0 = __expf(m0 - mn0), sc1 = __expf(m1 - mn1);
        l0 = l0 * sc0 + rs0;
        l1 = l1 * sc1 + rs1;
        m0 = mn0; m1 = mn1;
#pragma unroll
        for (int ot = 0; ot < 8; ot++) {
            o[ot][0] *= sc0; o[ot][1] *= sc0;
            o[ot][2] *= sc1; o[ot][3] *= sc1;
        }

        // PV: P single fp16, V single
#pragma unroll
        for (int kc = 0; kc < 2; kc++) {
            unsigned ph[4];
            {
                int n0i = 2 * kc, n1i = 2 * kc + 1;
                ph[0] = split_hi2(s[n0i][0], s[n0i][1]);
                ph[1] = split_hi2(s[n0i][2], s[n0i][3]);
                ph[2] = split_hi2(s[n1i][0], s[n1i][1]);
                ph[3] = split_hi2(s[n1i][2], s[n1i][3]);
            }
            int kk = kc * 16;
#pragma unroll
            for (int ot = 0; ot < 8; ot++) {
                unsigned bvh[2];
                bvh[0] = VTHF(ot * 8 + g, kk + 2 * t);
                bvh[1] = VTHF(ot * 8 + g, kk + 2 * t + 8);
                mma16816(o[ot], ph, bvh);
            }
        }
        __syncthreads();
    }

    bool deg0 = !(m0 > -1e8f);
    bool deg1 = !(m1 > -1e8f);
    float inv0 = deg0 ? 0.f : 1.f / l0;
    float inv1 = deg1 ? 0.f : 1.f / l1;
#pragma unroll
    for (int ot = 0; ot < 8; ot++) {
        int col = h * DK + ot * 8 + 2 * t;
        float2 o0 = { o[ot][0] * inv0, o[ot][1] * inv0 };
        float2 o1 = { o[ot][2] * inv1, o[ot][3] * inv1 };
        if (deg0) {
            float s0 = 0.f, s1 = 0.f;
            const __half* vp = &g_vh[(size_t)(b * SS) * DM + col];
            for (int kv = 0; kv < SS; kv++) {
                s0 += __half2float(vp[(size_t)kv * DM]);
                s1 += __half2float(vp[(size_t)kv * DM + 1]);
            }
            o0.x = s0 / SS; o0.y = s1 / SS;
        }
        if (deg1) {
            float s0 = 0.f, s1 = 0.f;
            const __half* vp = &g_vh[(size_t)(b * SS) * DM + col];
            for (int kv = 0; kv < SS; kv++) {
                s0 += __half2float(vp[(size_t)kv * DM]);
                s1 += __half2float(vp[(size_t)kv * DM + 1]);
            }
            o1.x = s0 / SS; o1.y = s1 / SS;
        }
        *(unsigned*)&g_aoh[(size_t)(b * SS + row0) * DM + col] = split_hi2(o0.x, o0.y);
        *(unsigned*)&g_aoh[(size_t)(b * SS + row1) * DM + col] = split_hi2(o1.x, o1.y);
    }
    if (t == 0) {
        int gi0 = (b * NH + h) * SS + row0;
        int gi1 = (b * NH + h) * SS + row1;
        g_m[gi0] = deg0 ? -1e9f : m0;
        g_l[gi0] = deg0 ? (float)SS : l0;
        g_m[gi1] = deg1 ? -1e9f : m1;
        g_l[gi1] = deg1 ? (float)SS : l1;
    }
}

// ============================================================
// Optional second pass: full attention probabilities
// ============================================================
__global__ __launch_bounds__(256) void attn_write(
    const int* __restrict__ token_ids, float* __restrict__ attn)
{
    int kvb = blockIdx.x, qb = blockIdx.y;
    int bh = blockIdx.z;
    int b = bh >> 4, h = bh & 15;
    int q0 = qb * 64, kv0 = kvb * 64;
    int tid = threadIdx.x;
    int tx = tid & 15, ty = tid >> 4;

    if (kv0 > q0 + 63) {
#pragma unroll
        for (int i = 0; i < 4; i++) {
            int q = q0 + ty * 4 + i;
            int gi = (b * NH + h) * SS + q;
            float m = g_m[gi];
            float val = (m <= -1e8f) ? (1.f / g_l[gi]) : 0.f;
            float4 o = { val, val, val, val };
            *(float4*)&attn[((size_t)(b * NH + h) * SS + q) * SS + kv0 + tx * 4] = o;
        }
        return;
    }

    __shared__ float Qs[64][65];
    __shared__ float Ks2[64][65];
    __shared__ int padf[64];
    {
        int r = tid >> 2;
        int d0 = (tid & 3) * 16;
        const float* qp = &g_q[(size_t)(b * SS + q0 + r) * DM + h * DK + d0];
        const float* kp = &g_k[(size_t)(b * SS + kv0 + r) * DM + h * DK + d0];
#pragma unroll
        for (int i = 0; i < 16; i += 4) {
            float4 v4 = *(const float4*)(qp + i);
            Qs[d0 + i + 0][r] = v4.x; Qs[d0 + i + 1][r] = v4.y;
            Qs[d0 + i + 2][r] = v4.z; Qs[d0 + i + 3][r] = v4.w;
            float4 k4 = *(const float4*)(kp + i);
            Ks2[d0 + i + 0][r] = k4.x; Ks2[d0 + i + 1][r] = k4.y;
            Ks2[d0 + i + 2][r] = k4.z; Ks2[d0 + i + 3][r] = k4.w;
        }
    }
    if (tid < 64) padf[tid] = (token_ids[b * SS + kv0 + tid] == 0);
    __syncthreads();

    float s[4][4];
#pragma unroll
    for (int i = 0; i < 4; i++)
#pragma unroll
        for (int j = 0; j < 4; j++) s[i][j] = 0.f;
#pragma unroll
    for (int kk = 0; kk < 64; kk++) {
        float qv[4], kv_[4];
#pragma unroll
        for (int i = 0; i < 4; i++) qv[i] = Qs[kk][ty * 4 + i];
#pragma unroll
        for (int j = 0; j < 4; j++) kv_[j] = Ks2[kk][tx * 4 + j];
#pragma unroll
        for (int i = 0; i < 4; i++)
#pragma unroll
            for (int j = 0; j < 4; j++)
                s[i][j] = fmaf(qv[i], kv_[j], s[i][j]);
    }
#pragma unroll
    for (int i = 0; i < 4; i++) {
        int q = q0 + ty * 4 + i;
        int gi = (b * NH + h) * SS + q;
        float m = g_m[gi];
        float invl = 1.f / g_l[gi];
        float4 o;
        float ov[4];
#pragma unroll
        for (int j = 0; j < 4; j++) {
            int kvi = kv0 + tx * 4 + j;
            float v = s[i][j] * 0.125f;
            if (kvi > q || padf[tx * 4 + j]) v = -1e9f;
            ov[j] = __expf(v - m) * invl;
        }
        o.x = ov[0]; o.y = ov[1]; o.z = ov[2]; o.w = ov[3];
        *(float4*)&attn[((size_t)(b * NH + h) * SS + q) * SS + kv0 + tx * 4] = o;
    }
}

// ============================================================
extern "C" void kernel_launch(void* const* d_in, const int* in_sizes, int n_in,
                              void* d_out, int out_size)
{
    const float* x  = (const float*)d_in[0];
    const int*  tok = (const int*)d_in[1];
    const float* wq = (const float*)d_in[2];
    const float* bq = (const float*)d_in[3];
    const float* wk = (const float*)d_in[4];
    const float* bk = (const float*)d_in[5];
    const float* wv = (const float*)d_in[6];
    const float* bv = (const float*)d_in[7];
    const float* wo = (const float*)d_in[8];
    const float* bo = (const float*)d_in[9];
    float* out = (float*)d_out;

    cudaFuncSetAttribute(gemm_pipe, cudaFuncAttributeMaxDynamicSharedMemorySize, GP_SMEM);
    cudaFuncSetAttribute(flash_tc2, cudaFuncAttributeMaxDynamicSharedMemorySize, F_SMEM);

    bool want_out  = (out_size != ATTN_ELEMS);
    bool want_attn = (out_size >= ATTN_ELEMS);
    float* attn_ptr = nullptr;
    if (out_size == ATTN_ELEMS) attn_ptr = out;
    else if (out_size >= OUT_ELEMS + ATTN_ELEMS) attn_ptr = out + OUT_ELEMS;

    dim3 bT(32, 8);

    conv_x<<<1024, 256>>>(x);
    transpose_w3<<<dim3(32, 32, 3), bT>>>(wq, wk, wv);
    gemm_pipe<<<dim3(24, 32), 256, GP_SMEM>>>(0, bq, bk, bv, nullptr, 1,
                                              want_attn ? 1 : 0);

    flash_tc2<<<dim3(SS / 128, NH, BB), 256, F_SMEM>>>(tok);

    if (want_out) {
        transpose_w3<<<dim3(32, 32, 1), bT>>>(wo, wo, wo);
        gemm_pipe<<<dim3(8, 32), 256, GP_SMEM>>>(1, bo, bo, bo, out, 0, 0);
    }
    if (want_attn && attn_ptr)
        attn_write<<<dim3(SS / 64, SS / 64, BB * NH), 256>>>(tok, attn_ptr);
}